// round 2
// baseline (speedup 1.0000x reference)
#include <cuda_runtime.h>
#include <math.h>

#define CC 256
#define HW 65536
#define NSWEEPS 10

// ---- scratch (static device arrays; no allocation anywhere) ----
__device__ float g_B[CC * HW];   // 64MB: per-channel working matrix, column-major
__device__ float g_T[CC * HW];   // 64MB: T = diag(f) * B^T A
__device__ float g_R[CC * HW];   // 64MB: recon = B * T
__device__ float g_mean[CC];
__device__ float g_max[CC];
__device__ int   g_k[CC];
__device__ float g_fact[CC * CC];
__device__ float g_cat[2 * HW];

// ---------------- stage 0: per-channel mean & max over HxW ----------------
__global__ void k_stats(const float* __restrict__ x) {
    int c = blockIdx.x, t = threadIdx.x;
    const float* xc = x + (size_t)c * HW;
    double s = 0.0;
    float m = -3.4e38f;
    for (int i = t; i < HW; i += 256) {
        float v = xc[i];
        s += (double)v;
        m = fmaxf(m, v);
    }
    __shared__ double ss[256];
    __shared__ float  sm[256];
    ss[t] = s; sm[t] = m;
    __syncthreads();
    for (int o = 128; o > 0; o >>= 1) {
        if (t < o) { ss[t] += ss[t + o]; sm[t] = fmaxf(sm[t], sm[t + o]); }
        __syncthreads();
    }
    if (t == 0) {
        g_mean[c] = (float)(ss[0] / (double)HW);
        g_max[c]  = sm[0];
    }
}

// ---------------- stage 1: channel attention -> k[c] ----------------
__global__ void k_att(const float* __restrict__ w1, const float* __restrict__ w2,
                      const int* __restrict__ kvp) {
    int t = threadIdx.x;
    __shared__ float  mu[256], mx[256];
    __shared__ double hA[16], hM[16];
    __shared__ double sy[256];
    __shared__ double ymin, ymax;
    mu[t] = g_mean[t]; mx[t] = g_max[t];
    __syncthreads();
    if (t < 16) {
        double a = 0.0, b = 0.0;
        for (int c2 = 0; c2 < 256; c2++) {
            double w = (double)w1[t * 256 + c2];
            a += w * (double)mu[c2];
            b += w * (double)mx[c2];
        }
        hA[t] = a > 0.0 ? a : 0.0;   // relu
        hM[t] = b > 0.0 ? b : 0.0;
    }
    __syncthreads();
    {
        double acc = 0.0;
        for (int r = 0; r < 16; r++)
            acc += (double)w2[t * 16 + r] * (hA[r] + hM[r]);
        sy[t] = 1.0 / (1.0 + exp(-acc));     // sigmoid(y_avg + y_max)
    }
    __syncthreads();
    if (t == 0) {
        double mn = sy[0], mv = sy[0];
        for (int i = 1; i < 256; i++) { mn = fmin(mn, sy[i]); mv = fmax(mv, sy[i]); }
        ymin = mn; ymax = mv;
    }
    __syncthreads();
    // kv hedge: accept int32 or float32 bit patterns
    int iv = *kvp;
    float fv = __int_as_float(iv);
    double kvd = (iv >= 0 && iv <= 1000000) ? (double)iv : (double)fv;
    double yc = (sy[t] - ymin) / (ymax - ymin + 1e-20);
    int k = (int)floor(256.0 * kvd * yc);
    if (k < 0) k = 0;
    if (k > 256) k = 256;
    g_k[t] = k;
}

// ---------------- stage 2: transpose x -> column-major B ----------------
__global__ void k_tr(const float* __restrict__ x) {
    __shared__ float tile[32][33];
    int c = blockIdx.z;
    int i0 = blockIdx.y * 32, j0 = blockIdx.x * 32;
    int tx = threadIdx.x, ty = threadIdx.y;
    const float* xc = x + (size_t)c * HW;
    float* bc = g_B + (size_t)c * HW;
#pragma unroll
    for (int m = 0; m < 4; m++)
        tile[ty + 8 * m][tx] = xc[(i0 + ty + 8 * m) * 256 + j0 + tx];
    __syncthreads();
#pragma unroll
    for (int m = 0; m < 4; m++)
        bc[(j0 + ty + 8 * m) * 256 + i0 + tx] = tile[tx][ty + 8 * m];
}

// ---------------- stage 3: one-sided Jacobi (Hestenes), no V ----------------
__global__ void __launch_bounds__(256) k_jacobi() {
    int c = blockIdx.x;
    float* B = g_B + (size_t)c * HW;
    int t = threadIdx.x, lane = t & 31, w = t >> 5;

    for (int sweep = 0; sweep < NSWEEPS; sweep++) {
        for (int r = 0; r < 255; r++) {
            for (int s = w; s < 128; s += 8) {
                // round-robin tournament: seat(0)=0 fixed, seats 1..255 rotate
                int p = (s == 0) ? 0 : (1 + (s - 1 + r) % 255);
                int q = 1 + (255 - s - 1 + r) % 255;   // seat 255-s (>=128, never 0)
                float* cp = B + p * 256;
                float* cq = B + q * 256;
                float bp[8], bq[8];
#pragma unroll
                for (int m = 0; m < 8; m++) {
                    bp[m] = cp[lane + 32 * m];
                    bq[m] = cq[lane + 32 * m];
                }
                float app = 0.f, aqq = 0.f, apq = 0.f;
#pragma unroll
                for (int m = 0; m < 8; m++) {
                    app = fmaf(bp[m], bp[m], app);
                    aqq = fmaf(bq[m], bq[m], aqq);
                    apq = fmaf(bp[m], bq[m], apq);
                }
#pragma unroll
                for (int o = 16; o > 0; o >>= 1) {
                    app += __shfl_xor_sync(0xFFFFFFFFu, app, o);
                    aqq += __shfl_xor_sync(0xFFFFFFFFu, aqq, o);
                    apq += __shfl_xor_sync(0xFFFFFFFFu, apq, o);
                }
                if (apq * apq > 1e-14f * app * aqq) {
                    float tau = (aqq - app) / (2.0f * apq);
                    float tt  = copysignf(1.0f, tau) / (fabsf(tau) + sqrtf(1.0f + tau * tau));
                    float cth = 1.0f / sqrtf(1.0f + tt * tt);
                    float sth = tt * cth;
#pragma unroll
                    for (int m = 0; m < 8; m++) {
                        float xp = bp[m], xq = bq[m];
                        cp[lane + 32 * m] = cth * xp - sth * xq;
                        cq[lane + 32 * m] = sth * xp + cth * xq;
                    }
                }
            }
            __syncthreads();
        }
    }
}

// ---------------- stage 4: column norms, rank, keep factor ----------------
__global__ void k_fact() {
    int c = blockIdx.x, t = threadIdx.x, lane = t & 31, w = t >> 5;
    __shared__ float s2[256];
    const float* B = g_B + (size_t)c * HW;
    for (int j = w; j < 256; j += 8) {
        const float* col = B + j * 256;
        float a = 0.f;
#pragma unroll
        for (int m = 0; m < 8; m++) {
            float v = col[lane + 32 * m];
            a = fmaf(v, v, a);
        }
#pragma unroll
        for (int o = 16; o > 0; o >>= 1) a += __shfl_xor_sync(0xFFFFFFFFu, a, o);
        if (lane == 0) s2[j] = a;
    }
    __syncthreads();
    float mys = s2[t];
    int kc = g_k[c];
    int rank = 0;
    for (int j = 0; j < 256; j++) {
        float v = s2[j];
        rank += (v > mys) || (v == mys && j < t);
    }
    g_fact[c * 256 + t] = (rank < kc) ? 1.0f / fmaxf(mys, 1e-20f) : 0.0f;
}

// ---------------- stage 5: T = diag(f) * B^T A ----------------
__global__ void k_gemmT(const float* __restrict__ x) {
    int c = blockIdx.z;
    int w0 = blockIdx.x * 32, j0 = blockIdx.y * 32;
    int tx = threadIdx.x, ty = threadIdx.y;
    __shared__ float Bs[32][33], As[32][33];
    const float* B = g_B + (size_t)c * HW;
    const float* A = x + (size_t)c * HW;
    float acc = 0.f;
    for (int kt = 0; kt < 8; kt++) {
        Bs[ty][tx] = B[(j0 + ty) * 256 + kt * 32 + tx];      // Bs[jj][ii] = B(i,j)
        As[ty][tx] = A[(kt * 32 + ty) * 256 + w0 + tx];      // As[ii][ww]
        __syncthreads();
#pragma unroll
        for (int i = 0; i < 32; i++) acc = fmaf(Bs[ty][i], As[i][tx], acc);
        __syncthreads();
    }
    g_T[(size_t)c * HW + (j0 + ty) * 256 + w0 + tx] = acc * g_fact[c * 256 + j0 + ty];
}

// ---------------- stage 6: R = B * T ----------------
__global__ void k_gemmR() {
    int c = blockIdx.z;
    int w0 = blockIdx.x * 32, i0 = blockIdx.y * 32;
    int tx = threadIdx.x, ty = threadIdx.y;
    __shared__ float Bs[32][33], Ts[32][33];
    const float* B = g_B + (size_t)c * HW;
    const float* T = g_T + (size_t)c * HW;
    float acc = 0.f;
    for (int kt = 0; kt < 8; kt++) {
        Bs[ty][tx] = B[(kt * 32 + ty) * 256 + i0 + tx];      // Bs[jj][ii] = B(i,j)
        Ts[ty][tx] = T[(kt * 32 + ty) * 256 + w0 + tx];      // Ts[jj][ww]
        __syncthreads();
#pragma unroll
        for (int j = 0; j < 32; j++) acc = fmaf(Bs[j][ty], Ts[j][tx], acc);
        __syncthreads();
    }
    g_R[(size_t)c * HW + (i0 + ty) * 256 + w0 + tx] = acc;
}

// ---------------- stage 7: channel mean & max of recon ----------------
__global__ void k_avgmax() {
    int pix = blockIdx.x * 1024 + threadIdx.x;
    float s = 0.f, m = -3.4e38f;
    for (int c = 0; c < 256; c++) {
        float v = g_R[(size_t)c * HW + pix];
        s += v;
        m = fmaxf(m, v);
    }
    g_cat[pix]      = s * (1.0f / 256.0f);
    g_cat[HW + pix] = m;
}

// ---------------- stage 8: 7x7 conv (pad 3) + EPS clamp + sigmoid ----------------
__global__ void k_conv(const float* __restrict__ cw, float* __restrict__ out) {
    __shared__ float wsm[98];
    int tx = threadIdx.x, ty = threadIdx.y;
    int tid = ty * 32 + tx;
    if (tid < 98) wsm[tid] = cw[tid];
    __syncthreads();
    int gx = blockIdx.x * 32 + tx;
    int gy = blockIdx.y * 8 + ty;
    float acc = 0.f;
#pragma unroll
    for (int ci = 0; ci < 2; ci++) {
#pragma unroll
        for (int kh = 0; kh < 7; kh++) {
            int iy = gy + kh - 3;
            if (iy < 0 || iy > 255) continue;
#pragma unroll
            for (int kw = 0; kw < 7; kw++) {
                int ix = gx + kw - 3;
                if (ix < 0 || ix > 255) continue;
                acc = fmaf(g_cat[ci * HW + iy * 256 + ix], wsm[ci * 49 + kh * 7 + kw], acc);
            }
        }
    }
    const float EPSF = 2.220446049250313e-16f;
    if (acc < EPSF) acc = EPSF;
    out[gy * 256 + gx] = 1.0f / (1.0f + expf(-acc));
}

// ---------------- launch ----------------
extern "C" void kernel_launch(void* const* d_in, const int* in_sizes, int n_in,
                              void* d_out, int out_size) {
    const float* x  = (const float*)d_in[0];
    const float* w1 = (const float*)d_in[1];
    const float* w2 = (const float*)d_in[2];
    const float* cw = (const float*)d_in[3];
    const int*   kv = (const int*)d_in[4];

    k_stats<<<256, 256>>>(x);
    k_att<<<1, 256>>>(w1, w2, kv);
    k_tr<<<dim3(8, 8, 256), dim3(32, 8)>>>(x);
    k_jacobi<<<256, 256>>>();
    k_fact<<<256, 256>>>();
    k_gemmT<<<dim3(8, 8, 256), dim3(32, 32)>>>(x);
    k_gemmR<<<dim3(8, 8, 256), dim3(32, 32)>>>();
    k_avgmax<<<64, 1024>>>();
    k_conv<<<dim3(8, 32), dim3(32, 8)>>>(cw, (float*)d_out);
}

// round 3
// speedup vs baseline: 1.4252x; 1.4252x over previous
#include <cuda_runtime.h>
#include <math.h>

#define CC 256
#define HW 65536
#define NSWMAX 14
#define ROTTHR 1e-12f   // relative off-diag threshold^2 (rel 1e-6)

// ---- scratch (static device arrays; no allocation anywhere) ----
__device__ float g_B[CC * HW];   // 64MB: per-channel working matrix, column-major
__device__ float g_T[CC * HW];   // 64MB: T = diag(f) * B^T A
__device__ float g_R[CC * HW];   // 64MB: recon = B * T
__device__ float g_mean[CC];
__device__ float g_max[CC];
__device__ int   g_k[CC];
__device__ float g_fact[CC * CC];
__device__ float g_cat[2 * HW];

// ---------------- stage 0: per-channel mean & max over HxW ----------------
__global__ void k_stats(const float* __restrict__ x) {
    int c = blockIdx.x, t = threadIdx.x;
    const float* xc = x + (size_t)c * HW;
    double s = 0.0;
    float m = -3.4e38f;
    for (int i = t; i < HW; i += 256) {
        float v = xc[i];
        s += (double)v;
        m = fmaxf(m, v);
    }
    __shared__ double ss[256];
    __shared__ float  sm[256];
    ss[t] = s; sm[t] = m;
    __syncthreads();
    for (int o = 128; o > 0; o >>= 1) {
        if (t < o) { ss[t] += ss[t + o]; sm[t] = fmaxf(sm[t], sm[t + o]); }
        __syncthreads();
    }
    if (t == 0) {
        g_mean[c] = (float)(ss[0] / (double)HW);
        g_max[c]  = sm[0];
    }
}

// ---------------- stage 1: channel attention -> k[c] ----------------
__global__ void k_att(const float* __restrict__ w1, const float* __restrict__ w2,
                      const int* __restrict__ kvp) {
    int t = threadIdx.x;
    __shared__ float  mu[256], mx[256];
    __shared__ double hA[16], hM[16];
    __shared__ double sy[256];
    __shared__ double ymin, ymax;
    mu[t] = g_mean[t]; mx[t] = g_max[t];
    __syncthreads();
    if (t < 16) {
        double a = 0.0, b = 0.0;
        for (int c2 = 0; c2 < 256; c2++) {
            double w = (double)w1[t * 256 + c2];
            a += w * (double)mu[c2];
            b += w * (double)mx[c2];
        }
        hA[t] = a > 0.0 ? a : 0.0;   // relu
        hM[t] = b > 0.0 ? b : 0.0;
    }
    __syncthreads();
    {
        double acc = 0.0;
        for (int r = 0; r < 16; r++)
            acc += (double)w2[t * 16 + r] * (hA[r] + hM[r]);
        sy[t] = 1.0 / (1.0 + exp(-acc));     // sigmoid(y_avg + y_max)
    }
    __syncthreads();
    if (t == 0) {
        double mn = sy[0], mv = sy[0];
        for (int i = 1; i < 256; i++) { mn = fmin(mn, sy[i]); mv = fmax(mv, sy[i]); }
        ymin = mn; ymax = mv;
    }
    __syncthreads();
    // kv hedge: accept int32 or float32 bit patterns
    int iv = *kvp;
    float fv = __int_as_float(iv);
    double kvd = (iv >= 0 && iv <= 1000000) ? (double)iv : (double)fv;
    double yc = (sy[t] - ymin) / (ymax - ymin + 1e-20);
    int k = (int)floor(256.0 * kvd * yc);
    if (k < 0) k = 0;
    if (k > 256) k = 256;
    g_k[t] = k;
}

// ---------------- stage 2: transpose x -> column-major B ----------------
__global__ void k_tr(const float* __restrict__ x) {
    __shared__ float tile[32][33];
    int c = blockIdx.z;
    int i0 = blockIdx.y * 32, j0 = blockIdx.x * 32;
    int tx = threadIdx.x, ty = threadIdx.y;
    const float* xc = x + (size_t)c * HW;
    float* bc = g_B + (size_t)c * HW;
#pragma unroll
    for (int m = 0; m < 4; m++)
        tile[ty + 8 * m][tx] = xc[(i0 + ty + 8 * m) * 256 + j0 + tx];
    __syncthreads();
#pragma unroll
    for (int m = 0; m < 4; m++)
        bc[(j0 + ty + 8 * m) * 256 + i0 + tx] = tile[tx][ty + 8 * m];
}

// ---------------- stage 3: blocked one-sided Jacobi (Hestenes), no V ----------------
// 8 blocks of 32 columns. Intra-block rotations in smem; cross-block rotations
// pair a register-resident column (warp-owned) with a smem column, with
// incremental norm maintenance (one dot product per pair).
__global__ void __launch_bounds__(1024) k_jacobi() {
    int c = blockIdx.x;
    float* Bg = g_B + (size_t)c * HW;
    int t = threadIdx.x, lane = t & 31, w = t >> 5;

    __shared__ float sj[8192];     // 32KB: one 32-column block
    __shared__ float snj[32];      // column norms^2 of smem block
    __shared__ int s_flag;

    for (int sweep = 0; sweep < NSWMAX; sweep++) {
        if (t == 0) s_flag = 0;
        __syncthreads();
        for (int bi = 0; bi < 8; bi++) {
            // ---- load block bi -> smem
            for (int idx = t; idx < 8192; idx += 1024)
                sj[idx] = Bg[bi * 8192 + idx];
            __syncthreads();
            // ---- intra-block round-robin: 31 rounds x 16 pairs (warps 0..15)
            for (int r = 0; r < 31; r++) {
                if (w < 16) {
                    int p = (w == 0) ? 0 : 1 + (w - 1 + r) % 31;
                    int q = 1 + (30 - w + r) % 31;
                    float4* cp = (float4*)(sj + p * 256);
                    float4* cq = (float4*)(sj + q * 256);
                    float4 p0 = cp[lane * 2], p1 = cp[lane * 2 + 1];
                    float4 q0 = cq[lane * 2], q1 = cq[lane * 2 + 1];
                    float bp[8] = {p0.x, p0.y, p0.z, p0.w, p1.x, p1.y, p1.z, p1.w};
                    float bq[8] = {q0.x, q0.y, q0.z, q0.w, q1.x, q1.y, q1.z, q1.w};
                    float app = 0.f, aqq = 0.f, apq = 0.f;
#pragma unroll
                    for (int m = 0; m < 8; m++) {
                        app = fmaf(bp[m], bp[m], app);
                        aqq = fmaf(bq[m], bq[m], aqq);
                        apq = fmaf(bp[m], bq[m], apq);
                    }
#pragma unroll
                    for (int o = 16; o > 0; o >>= 1) {
                        app += __shfl_xor_sync(0xFFFFFFFFu, app, o);
                        aqq += __shfl_xor_sync(0xFFFFFFFFu, aqq, o);
                        apq += __shfl_xor_sync(0xFFFFFFFFu, apq, o);
                    }
                    if (apq * apq > ROTTHR * app * aqq) {
                        float tau = (aqq - app) / (2.0f * apq);
                        float tt  = copysignf(1.0f, tau) / (fabsf(tau) + sqrtf(1.0f + tau * tau));
                        float cth = 1.0f / sqrtf(1.0f + tt * tt);
                        float sth = tt * cth;
                        float np[8], nq[8];
#pragma unroll
                        for (int m = 0; m < 8; m++) {
                            np[m] = cth * bp[m] - sth * bq[m];
                            nq[m] = sth * bp[m] + cth * bq[m];
                        }
                        cp[lane * 2]     = make_float4(np[0], np[1], np[2], np[3]);
                        cp[lane * 2 + 1] = make_float4(np[4], np[5], np[6], np[7]);
                        cq[lane * 2]     = make_float4(nq[0], nq[1], nq[2], nq[3]);
                        cq[lane * 2 + 1] = make_float4(nq[4], nq[5], nq[6], nq[7]);
                        if (lane == 0) s_flag = 1;
                    }
                }
                __syncthreads();
            }
            // ---- move column w of block bi into registers + its norm
            float rp[8];
            {
                float4 v0 = ((float4*)(sj + w * 256))[lane * 2];
                float4 v1 = ((float4*)(sj + w * 256))[lane * 2 + 1];
                rp[0] = v0.x; rp[1] = v0.y; rp[2] = v0.z; rp[3] = v0.w;
                rp[4] = v1.x; rp[5] = v1.y; rp[6] = v1.z; rp[7] = v1.w;
            }
            float app = 0.f;
#pragma unroll
            for (int m = 0; m < 8; m++) app = fmaf(rp[m], rp[m], app);
#pragma unroll
            for (int o = 16; o > 0; o >>= 1) app += __shfl_xor_sync(0xFFFFFFFFu, app, o);

            // ---- cross-block phase
            for (int bj = bi + 1; bj < 8; bj++) {
                __syncthreads();                       // sj about to be overwritten
                for (int idx = t; idx < 8192; idx += 1024)
                    sj[idx] = Bg[bj * 8192 + idx];
                __syncthreads();
                {   // norms of bj columns (warp w -> col w)
                    float4 v0 = ((float4*)(sj + w * 256))[lane * 2];
                    float4 v1 = ((float4*)(sj + w * 256))[lane * 2 + 1];
                    float a = v0.x*v0.x + v0.y*v0.y + v0.z*v0.z + v0.w*v0.w
                            + v1.x*v1.x + v1.y*v1.y + v1.z*v1.z + v1.w*v1.w;
#pragma unroll
                    for (int o = 16; o > 0; o >>= 1) a += __shfl_xor_sync(0xFFFFFFFFu, a, o);
                    if (lane == 0) snj[w] = a;
                }
                __syncthreads();
                for (int r = 0; r < 32; r++) {
                    int q = (w + r) & 31;
                    float4* cq = (float4*)(sj + q * 256);
                    float4 q0 = cq[lane * 2], q1 = cq[lane * 2 + 1];
                    float bq[8] = {q0.x, q0.y, q0.z, q0.w, q1.x, q1.y, q1.z, q1.w};
                    float apq = 0.f;
#pragma unroll
                    for (int m = 0; m < 8; m++) apq = fmaf(rp[m], bq[m], apq);
#pragma unroll
                    for (int o = 16; o > 0; o >>= 1) apq += __shfl_xor_sync(0xFFFFFFFFu, apq, o);
                    float aqq = snj[q];
                    if (apq * apq > ROTTHR * app * aqq) {
                        float tau = (aqq - app) / (2.0f * apq);
                        float tt  = copysignf(1.0f, tau) / (fabsf(tau) + sqrtf(1.0f + tau * tau));
                        float cth = 1.0f / sqrtf(1.0f + tt * tt);
                        float sth = tt * cth;
                        float nq[8];
#pragma unroll
                        for (int m = 0; m < 8; m++) {
                            float xp = rp[m];
                            nq[m] = sth * xp + cth * bq[m];
                            rp[m] = cth * xp - sth * bq[m];
                        }
                        cq[lane * 2]     = make_float4(nq[0], nq[1], nq[2], nq[3]);
                        cq[lane * 2 + 1] = make_float4(nq[4], nq[5], nq[6], nq[7]);
                        app = app - tt * apq;
                        if (lane == 0) {
                            snj[q] = aqq + tt * apq;
                            s_flag = 1;
                        }
                    }
                    __syncthreads();
                }
                // store bj back (round loop ended with a sync)
                for (int idx = t; idx < 8192; idx += 1024)
                    Bg[bj * 8192 + idx] = sj[idx];
            }
            __syncthreads();   // bj store reads done before sj reuse next bi
            // ---- store register column back
            ((float4*)(Bg + (bi * 32 + w) * 256))[lane * 2] =
                make_float4(rp[0], rp[1], rp[2], rp[3]);
            ((float4*)(Bg + (bi * 32 + w) * 256))[lane * 2 + 1] =
                make_float4(rp[4], rp[5], rp[6], rp[7]);
            __syncthreads();
        }
        __syncthreads();
        int done = (s_flag == 0);
        __syncthreads();
        if (done) break;
    }
}

// ---------------- stage 4: column norms, rank, keep factor ----------------
__global__ void k_fact() {
    int c = blockIdx.x, t = threadIdx.x, lane = t & 31, w = t >> 5;
    __shared__ float s2[256];
    const float* B = g_B + (size_t)c * HW;
    for (int j = w; j < 256; j += 8) {
        const float* col = B + j * 256;
        float a = 0.f;
#pragma unroll
        for (int m = 0; m < 8; m++) {
            float v = col[lane + 32 * m];
            a = fmaf(v, v, a);
        }
#pragma unroll
        for (int o = 16; o > 0; o >>= 1) a += __shfl_xor_sync(0xFFFFFFFFu, a, o);
        if (lane == 0) s2[j] = a;
    }
    __syncthreads();
    float mys = s2[t];
    int kc = g_k[c];
    int rank = 0;
    for (int j = 0; j < 256; j++) {
        float v = s2[j];
        rank += (v > mys) || (v == mys && j < t);
    }
    g_fact[c * 256 + t] = (rank < kc) ? 1.0f / fmaxf(mys, 1e-20f) : 0.0f;
}

// ---------------- stage 5: T = diag(f) * B^T A  (C = M*N, M row-major = B^T) ----------
__global__ void __launch_bounds__(256) k_gemmT(const float* __restrict__ x) {
    int c = blockIdx.z;
    const float* M = g_B + (size_t)c * HW;   // M[j][i] = B(i,j)
    const float* N = x + (size_t)c * HW;     // A row-major
    float* C = g_T + (size_t)c * HW;
    int m0 = blockIdx.y * 64, n0 = blockIdx.x * 64;
    __shared__ float Ms[16][68], Ns[16][68];
    int t = threadIdx.x;
    int tx = t & 15, ty = t >> 4;
    float acc[4][4] = {};
    for (int k0 = 0; k0 < 256; k0 += 16) {
#pragma unroll
        for (int u = 0; u < 4; u++) {
            int id = t + 256 * u;
            int kk = id & 15, mm = id >> 4;
            Ms[kk][mm] = M[(m0 + mm) * 256 + k0 + kk];
        }
#pragma unroll
        for (int u = 0; u < 4; u++) {
            int id = t + 256 * u;
            int kk = id >> 6, nn = id & 63;
            Ns[kk][nn] = N[(k0 + kk) * 256 + n0 + nn];
        }
        __syncthreads();
#pragma unroll
        for (int kk = 0; kk < 16; kk++) {
            float a[4], b[4];
#pragma unroll
            for (int i = 0; i < 4; i++) a[i] = Ms[kk][ty * 4 + i];
#pragma unroll
            for (int j = 0; j < 4; j++) b[j] = Ns[kk][tx * 4 + j];
#pragma unroll
            for (int i = 0; i < 4; i++)
#pragma unroll
                for (int j = 0; j < 4; j++) acc[i][j] = fmaf(a[i], b[j], acc[i][j]);
        }
        __syncthreads();
    }
    const float* f = g_fact + c * 256;
#pragma unroll
    for (int i = 0; i < 4; i++) {
        float fi = f[m0 + ty * 4 + i];
#pragma unroll
        for (int j = 0; j < 4; j++)
            C[(m0 + ty * 4 + i) * 256 + n0 + tx * 4 + j] = acc[i][j] * fi;
    }
}

// ---------------- stage 6: R = B * T  (= M^T * N with M as above) ----------------
__global__ void __launch_bounds__(256) k_gemmR() {
    int c = blockIdx.z;
    const float* M = g_B + (size_t)c * HW;   // M[j][i] = B(i,j); need M^T * T
    const float* N = g_T + (size_t)c * HW;
    float* C = g_R + (size_t)c * HW;
    int m0 = blockIdx.y * 64, n0 = blockIdx.x * 64;
    __shared__ float Ms[16][68], Ns[16][68];
    int t = threadIdx.x;
    int tx = t & 15, ty = t >> 4;
    float acc[4][4] = {};
    for (int k0 = 0; k0 < 256; k0 += 16) {
#pragma unroll
        for (int u = 0; u < 4; u++) {
            int id = t + 256 * u;
            int kk = id >> 6, mm = id & 63;
            Ms[kk][mm] = M[(k0 + kk) * 256 + m0 + mm];   // M^T tile, coalesced
        }
#pragma unroll
        for (int u = 0; u < 4; u++) {
            int id = t + 256 * u;
            int kk = id >> 6, nn = id & 63;
            Ns[kk][nn] = N[(k0 + kk) * 256 + n0 + nn];
        }
        __syncthreads();
#pragma unroll
        for (int kk = 0; kk < 16; kk++) {
            float a[4], b[4];
#pragma unroll
            for (int i = 0; i < 4; i++) a[i] = Ms[kk][ty * 4 + i];
#pragma unroll
            for (int j = 0; j < 4; j++) b[j] = Ns[kk][tx * 4 + j];
#pragma unroll
            for (int i = 0; i < 4; i++)
#pragma unroll
                for (int j = 0; j < 4; j++) acc[i][j] = fmaf(a[i], b[j], acc[i][j]);
        }
        __syncthreads();
    }
#pragma unroll
    for (int i = 0; i < 4; i++)
#pragma unroll
        for (int j = 0; j < 4; j++)
            C[(m0 + ty * 4 + i) * 256 + n0 + tx * 4 + j] = acc[i][j];
}

// ---------------- stage 7: channel mean & max of recon ----------------
__global__ void k_avgmax() {
    int pix = blockIdx.x * 1024 + threadIdx.x;
    float s = 0.f, m = -3.4e38f;
    for (int c = 0; c < 256; c++) {
        float v = g_R[(size_t)c * HW + pix];
        s += v;
        m = fmaxf(m, v);
    }
    g_cat[pix]      = s * (1.0f / 256.0f);
    g_cat[HW + pix] = m;
}

// ---------------- stage 8: 7x7 conv (pad 3) + EPS clamp + sigmoid ----------------
__global__ void k_conv(const float* __restrict__ cw, float* __restrict__ out) {
    __shared__ float wsm[98];
    int tx = threadIdx.x, ty = threadIdx.y;
    int tid = ty * 32 + tx;
    if (tid < 98) wsm[tid] = cw[tid];
    __syncthreads();
    int gx = blockIdx.x * 32 + tx;
    int gy = blockIdx.y * 8 + ty;
    float acc = 0.f;
#pragma unroll
    for (int ci = 0; ci < 2; ci++) {
#pragma unroll
        for (int kh = 0; kh < 7; kh++) {
            int iy = gy + kh - 3;
            if (iy < 0 || iy > 255) continue;
#pragma unroll
            for (int kw = 0; kw < 7; kw++) {
                int ix = gx + kw - 3;
                if (ix < 0 || ix > 255) continue;
                acc = fmaf(g_cat[ci * HW + iy * 256 + ix], wsm[ci * 49 + kh * 7 + kw], acc);
            }
        }
    }
    const float EPSF = 2.220446049250313e-16f;
    if (acc < EPSF) acc = EPSF;
    out[gy * 256 + gx] = 1.0f / (1.0f + expf(-acc));
}

// ---------------- launch ----------------
extern "C" void kernel_launch(void* const* d_in, const int* in_sizes, int n_in,
                              void* d_out, int out_size) {
    const float* x  = (const float*)d_in[0];
    const float* w1 = (const float*)d_in[1];
    const float* w2 = (const float*)d_in[2];
    const float* cw = (const float*)d_in[3];
    const int*   kv = (const int*)d_in[4];

    k_stats<<<256, 256>>>(x);
    k_att<<<1, 256>>>(w1, w2, kv);
    k_tr<<<dim3(8, 8, 256), dim3(32, 8)>>>(x);
    k_jacobi<<<256, 1024>>>();
    k_fact<<<256, 256>>>();
    k_gemmT<<<dim3(4, 4, 256), 256>>>(x);
    k_gemmR<<<dim3(4, 4, 256), 256>>>();
    k_avgmax<<<64, 1024>>>();
    k_conv<<<dim3(8, 32), dim3(32, 8)>>>(cw, (float*)d_out);
}

// round 7
// speedup vs baseline: 1.7622x; 1.2365x over previous
#include <cuda_runtime.h>
#include <math.h>

#define CC 256
#define HW 65536
#define NSWMAX 12
#define ROTTHR 1e-10f   // relative off-diag threshold^2 (rel 1e-5)

// ---- scratch (static device arrays; no allocation anywhere) ----
__device__ float g_B[CC * HW];   // 64MB: per-channel working matrix, column-major
__device__ float g_T[CC * HW];   // 64MB: T = diag(f) * B^T A
__device__ float g_R[CC * HW];   // 64MB: recon = B * T
__device__ float g_mean[CC];
__device__ float g_max[CC];
__device__ int   g_k[CC];
__device__ float g_fact[CC * CC];
__device__ float g_cat[2 * HW];

__device__ __forceinline__ float warp_sum(float a) {
#pragma unroll
    for (int o = 16; o > 0; o >>= 1) a += __shfl_xor_sync(0xFFFFFFFFu, a, o);
    return a;
}

// ---------------- stage 0: per-channel mean & max over HxW ----------------
__global__ void k_stats(const float* __restrict__ x) {
    int c = blockIdx.x, t = threadIdx.x;
    const float* xc = x + (size_t)c * HW;
    double s = 0.0;
    float m = -3.4e38f;
    for (int i = t; i < HW; i += 256) {
        float v = xc[i];
        s += (double)v;
        m = fmaxf(m, v);
    }
    __shared__ double ss[256];
    __shared__ float  sm[256];
    ss[t] = s; sm[t] = m;
    __syncthreads();
    for (int o = 128; o > 0; o >>= 1) {
        if (t < o) { ss[t] += ss[t + o]; sm[t] = fmaxf(sm[t], sm[t + o]); }
        __syncthreads();
    }
    if (t == 0) {
        g_mean[c] = (float)(ss[0] / (double)HW);
        g_max[c]  = sm[0];
    }
}

// ---------------- stage 1: channel attention -> k[c] ----------------
__global__ void k_att(const float* __restrict__ w1, const float* __restrict__ w2,
                      const int* __restrict__ kvp) {
    int t = threadIdx.x;
    __shared__ float  mu[256], mx[256];
    __shared__ double hA[16], hM[16];
    __shared__ double sy[256];
    __shared__ double ymin, ymax;
    mu[t] = g_mean[t]; mx[t] = g_max[t];
    __syncthreads();
    if (t < 16) {
        double a = 0.0, b = 0.0;
        for (int c2 = 0; c2 < 256; c2++) {
            double w = (double)w1[t * 256 + c2];
            a += w * (double)mu[c2];
            b += w * (double)mx[c2];
        }
        hA[t] = a > 0.0 ? a : 0.0;   // relu
        hM[t] = b > 0.0 ? b : 0.0;
    }
    __syncthreads();
    {
        double acc = 0.0;
        for (int r = 0; r < 16; r++)
            acc += (double)w2[t * 16 + r] * (hA[r] + hM[r]);
        sy[t] = 1.0 / (1.0 + exp(-acc));     // sigmoid(y_avg + y_max)
    }
    __syncthreads();
    if (t == 0) {
        double mn = sy[0], mv = sy[0];
        for (int i = 1; i < 256; i++) { mn = fmin(mn, sy[i]); mv = fmax(mv, sy[i]); }
        ymin = mn; ymax = mv;
    }
    __syncthreads();
    // kv hedge: accept int32 or float32 bit patterns
    int iv = *kvp;
    float fv = __int_as_float(iv);
    double kvd = (iv >= 0 && iv <= 1000000) ? (double)iv : (double)fv;
    double yc = (sy[t] - ymin) / (ymax - ymin + 1e-20);
    int k = (int)floor(256.0 * kvd * yc);
    if (k < 0) k = 0;
    if (k > 256) k = 256;
    g_k[t] = k;
}

// ---------------- stage 2: transpose x -> column-major B ----------------
__global__ void k_tr(const float* __restrict__ x) {
    __shared__ float tile[32][33];
    int c = blockIdx.z;
    int i0 = blockIdx.y * 32, j0 = blockIdx.x * 32;
    int tx = threadIdx.x, ty = threadIdx.y;
    const float* xc = x + (size_t)c * HW;
    float* bc = g_B + (size_t)c * HW;
#pragma unroll
    for (int m = 0; m < 4; m++)
        tile[ty + 8 * m][tx] = xc[(i0 + ty + 8 * m) * 256 + j0 + tx];
    __syncthreads();
#pragma unroll
    for (int m = 0; m < 4; m++)
        bc[(j0 + ty + 8 * m) * 256 + i0 + tx] = tile[tx][ty + 8 * m];
}

// ---------------- stage 3: blocked one-sided Jacobi (Hestenes), no V ----------------
// 512 threads (16 warps), 2 CTAs/SM. 8 blocks of 32 columns.
// Intra-block: 31 tournament rounds x 16 warp-pairs in smem, cached norms.
// Cross-block: each warp holds 2 register columns (w, w+16); per round rotates
// them against smem columns q0=(w+r)&31 and q1=(q0+16)&31 (all 32 disjoint).
__global__ void __launch_bounds__(512, 2) k_jacobi() {
    int c = blockIdx.x;
    float* Bg = g_B + (size_t)c * HW;
    int t = threadIdx.x, lane = t & 31, w = t >> 5;   // w in 0..15

    __shared__ float sj[8192];     // 32KB: one 32-column block
    __shared__ float snj[32];      // column norms^2 of smem block
    __shared__ int s_flag;

    for (int sweep = 0; sweep < NSWMAX; sweep++) {
        if (t == 0) s_flag = 0;
        __syncthreads();
        for (int bi = 0; bi < 8; bi++) {
            // ---- load block bi: warp w loads cols w, w+16 + computes norms
#pragma unroll
            for (int h = 0; h < 2; h++) {
                int col = w + 16 * h;
                const float4* src = (const float4*)(Bg + (bi * 32 + col) * 256);
                float4* dst = (float4*)(sj + col * 256);
                float4 v0 = src[lane * 2], v1 = src[lane * 2 + 1];
                dst[lane * 2] = v0; dst[lane * 2 + 1] = v1;
                float a = v0.x*v0.x + v0.y*v0.y + v0.z*v0.z + v0.w*v0.w
                        + v1.x*v1.x + v1.y*v1.y + v1.z*v1.z + v1.w*v1.w;
                a = warp_sum(a);
                if (lane == 0) snj[col] = a;
            }
            __syncthreads();
            // ---- intra-block tournament: 31 rounds x 16 pairs
            for (int r = 0; r < 31; r++) {
                int p = (w == 0) ? 0 : 1 + (w - 1 + r) % 31;
                int q = 1 + (30 - w + r) % 31;
                float4* cp = (float4*)(sj + p * 256);
                float4* cq = (float4*)(sj + q * 256);
                float4 p0 = cp[lane * 2], p1 = cp[lane * 2 + 1];
                float4 q0 = cq[lane * 2], q1 = cq[lane * 2 + 1];
                float apq = p0.x * q0.x;
                apq = fmaf(p0.y, q0.y, apq);
                apq = fmaf(p0.z, q0.z, apq);
                apq = fmaf(p0.w, q0.w, apq);
                apq = fmaf(p1.x, q1.x, apq);
                apq = fmaf(p1.y, q1.y, apq);
                apq = fmaf(p1.z, q1.z, apq);
                apq = fmaf(p1.w, q1.w, apq);
                apq = warp_sum(apq);
                float app = snj[p], aqq = snj[q];
                if (apq * apq > ROTTHR * app * aqq) {
                    float tau = (aqq - app) / (2.0f * apq);
                    float tt  = copysignf(1.0f, tau) / (fabsf(tau) + sqrtf(1.0f + tau * tau));
                    float cth = 1.0f / sqrtf(1.0f + tt * tt);
                    float sth = tt * cth;
                    float4 np, nq;
                    np.x = cth*p0.x - sth*q0.x;  nq.x = sth*p0.x + cth*q0.x;
                    np.y = cth*p0.y - sth*q0.y;  nq.y = sth*p0.y + cth*q0.y;
                    np.z = cth*p0.z - sth*q0.z;  nq.z = sth*p0.z + cth*q0.z;
                    np.w = cth*p0.w - sth*q0.w;  nq.w = sth*p0.w + cth*q0.w;
                    cp[lane * 2] = np;  cq[lane * 2] = nq;
                    np.x = cth*p1.x - sth*q1.x;  nq.x = sth*p1.x + cth*q1.x;
                    np.y = cth*p1.y - sth*q1.y;  nq.y = sth*p1.y + cth*q1.y;
                    np.z = cth*p1.z - sth*q1.z;  nq.z = sth*p1.z + cth*q1.z;
                    np.w = cth*p1.w - sth*q1.w;  nq.w = sth*p1.w + cth*q1.w;
                    cp[lane * 2 + 1] = np;  cq[lane * 2 + 1] = nq;
                    if (lane == 0) {
                        snj[p] = app - tt * apq;
                        snj[q] = aqq + tt * apq;
                        s_flag = 1;
                    }
                }
                __syncthreads();
            }
            // ---- move cols w and w+16 of bi into registers (exact norms)
            float rp0[8], rp1[8], app0, app1;
            {
                const float4* c0 = (const float4*)(sj + w * 256);
                float4 a0 = c0[lane * 2], a1 = c0[lane * 2 + 1];
                rp0[0]=a0.x; rp0[1]=a0.y; rp0[2]=a0.z; rp0[3]=a0.w;
                rp0[4]=a1.x; rp0[5]=a1.y; rp0[6]=a1.z; rp0[7]=a1.w;
                float a = 0.f;
#pragma unroll
                for (int m = 0; m < 8; m++) a = fmaf(rp0[m], rp0[m], a);
                app0 = warp_sum(a);
                const float4* c1 = (const float4*)(sj + (w + 16) * 256);
                float4 b0 = c1[lane * 2], b1 = c1[lane * 2 + 1];
                rp1[0]=b0.x; rp1[1]=b0.y; rp1[2]=b0.z; rp1[3]=b0.w;
                rp1[4]=b1.x; rp1[5]=b1.y; rp1[6]=b1.z; rp1[7]=b1.w;
                float b = 0.f;
#pragma unroll
                for (int m = 0; m < 8; m++) b = fmaf(rp1[m], rp1[m], b);
                app1 = warp_sum(b);
            }
            // ---- cross-block phase
            for (int bj = bi + 1; bj < 8; bj++) {
                // load bj (own cols — same-warp ordering vs. prior reads)
#pragma unroll
                for (int h = 0; h < 2; h++) {
                    int col = w + 16 * h;
                    const float4* src = (const float4*)(Bg + (bj * 32 + col) * 256);
                    float4* dst = (float4*)(sj + col * 256);
                    float4 v0 = src[lane * 2], v1 = src[lane * 2 + 1];
                    dst[lane * 2] = v0; dst[lane * 2 + 1] = v1;
                    float a = v0.x*v0.x + v0.y*v0.y + v0.z*v0.z + v0.w*v0.w
                            + v1.x*v1.x + v1.y*v1.y + v1.z*v1.z + v1.w*v1.w;
                    a = warp_sum(a);
                    if (lane == 0) snj[col] = a;
                }
                __syncthreads();
                for (int r = 0; r < 32; r++) {
                    int q0i = (w + r) & 31;
                    int q1i = (q0i + 16) & 31;
                    float4* cq0 = (float4*)(sj + q0i * 256);
                    float4* cq1 = (float4*)(sj + q1i * 256);
                    float4 x0 = cq0[lane * 2], x1 = cq0[lane * 2 + 1];
                    float4 y0 = cq1[lane * 2], y1 = cq1[lane * 2 + 1];
                    float bq0[8] = {x0.x,x0.y,x0.z,x0.w,x1.x,x1.y,x1.z,x1.w};
                    float bq1[8] = {y0.x,y0.y,y0.z,y0.w,y1.x,y1.y,y1.z,y1.w};
                    float d0 = 0.f, d1 = 0.f;
#pragma unroll
                    for (int m = 0; m < 8; m++) {
                        d0 = fmaf(rp0[m], bq0[m], d0);
                        d1 = fmaf(rp1[m], bq1[m], d1);
                    }
#pragma unroll
                    for (int o = 16; o > 0; o >>= 1) {   // interleaved chains
                        d0 += __shfl_xor_sync(0xFFFFFFFFu, d0, o);
                        d1 += __shfl_xor_sync(0xFFFFFFFFu, d1, o);
                    }
                    float aqq0 = snj[q0i], aqq1 = snj[q1i];
                    if (d0 * d0 > ROTTHR * app0 * aqq0) {
                        float tau = (aqq0 - app0) / (2.0f * d0);
                        float tt  = copysignf(1.0f, tau) / (fabsf(tau) + sqrtf(1.0f + tau * tau));
                        float cth = 1.0f / sqrtf(1.0f + tt * tt);
                        float sth = tt * cth;
                        float4 nv;
                        nv.x = fmaf(sth, rp0[0], cth * bq0[0]);
                        nv.y = fmaf(sth, rp0[1], cth * bq0[1]);
                        nv.z = fmaf(sth, rp0[2], cth * bq0[2]);
                        nv.w = fmaf(sth, rp0[3], cth * bq0[3]);
                        cq0[lane * 2] = nv;
                        nv.x = fmaf(sth, rp0[4], cth * bq0[4]);
                        nv.y = fmaf(sth, rp0[5], cth * bq0[5]);
                        nv.z = fmaf(sth, rp0[6], cth * bq0[6]);
                        nv.w = fmaf(sth, rp0[7], cth * bq0[7]);
                        cq0[lane * 2 + 1] = nv;
#pragma unroll
                        for (int m = 0; m < 8; m++)
                            rp0[m] = fmaf(cth, rp0[m], -sth * bq0[m]);
                        app0 = app0 - tt * d0;
                        if (lane == 0) { snj[q0i] = aqq0 + tt * d0; s_flag = 1; }
                    }
                    if (d1 * d1 > ROTTHR * app1 * aqq1) {
                        float tau = (aqq1 - app1) / (2.0f * d1);
                        float tt  = copysignf(1.0f, tau) / (fabsf(tau) + sqrtf(1.0f + tau * tau));
                        float cth = 1.0f / sqrtf(1.0f + tt * tt);
                        float sth = tt * cth;
                        float4 nv;
                        nv.x = fmaf(sth, rp1[0], cth * bq1[0]);
                        nv.y = fmaf(sth, rp1[1], cth * bq1[1]);
                        nv.z = fmaf(sth, rp1[2], cth * bq1[2]);
                        nv.w = fmaf(sth, rp1[3], cth * bq1[3]);
                        cq1[lane * 2] = nv;
                        nv.x = fmaf(sth, rp1[4], cth * bq1[4]);
                        nv.y = fmaf(sth, rp1[5], cth * bq1[5]);
                        nv.z = fmaf(sth, rp1[6], cth * bq1[6]);
                        nv.w = fmaf(sth, rp1[7], cth * bq1[7]);
                        cq1[lane * 2 + 1] = nv;
#pragma unroll
                        for (int m = 0; m < 8; m++)
                            rp1[m] = fmaf(cth, rp1[m], -sth * bq1[m]);
                        app1 = app1 - tt * d1;
                        if (lane == 0) { snj[q1i] = aqq1 + tt * d1; s_flag = 1; }
                    }
                    __syncthreads();
                }
                // store bj back (own cols; round loop ended with barrier)
#pragma unroll
                for (int h = 0; h < 2; h++) {
                    int col = w + 16 * h;
                    float4* dst = (float4*)(Bg + (bj * 32 + col) * 256);
                    const float4* src = (const float4*)(sj + col * 256);
                    dst[lane * 2] = src[lane * 2];
                    dst[lane * 2 + 1] = src[lane * 2 + 1];
                }
            }
            // ---- store register columns back
            ((float4*)(Bg + (bi * 32 + w) * 256))[lane * 2] =
                make_float4(rp0[0], rp0[1], rp0[2], rp0[3]);
            ((float4*)(Bg + (bi * 32 + w) * 256))[lane * 2 + 1] =
                make_float4(rp0[4], rp0[5], rp0[6], rp0[7]);
            ((float4*)(Bg + (bi * 32 + w + 16) * 256))[lane * 2] =
                make_float4(rp1[0], rp1[1], rp1[2], rp1[3]);
            ((float4*)(Bg + (bi * 32 + w + 16) * 256))[lane * 2 + 1] =
                make_float4(rp1[4], rp1[5], rp1[6], rp1[7]);
            __syncthreads();
        }
        __syncthreads();
        int done = (s_flag == 0);
        __syncthreads();
        if (done) break;
    }
}

// ---------------- stage 4: column norms, rank, keep factor ----------------
__global__ void k_fact() {
    int c = blockIdx.x, t = threadIdx.x, lane = t & 31, w = t >> 5;
    __shared__ float s2[256];
    const float* B = g_B + (size_t)c * HW;
    for (int j = w; j < 256; j += 8) {
        const float* col = B + j * 256;
        float a = 0.f;
#pragma unroll
        for (int m = 0; m < 8; m++) {
            float v = col[lane + 32 * m];
            a = fmaf(v, v, a);
        }
        a = warp_sum(a);
        if (lane == 0) s2[j] = a;
    }
    __syncthreads();
    float mys = s2[t];
    int kc = g_k[c];
    int rank = 0;
    for (int j = 0; j < 256; j++) {
        float v = s2[j];
        rank += (v > mys) || (v == mys && j < t);
    }
    g_fact[c * 256 + t] = (rank < kc) ? 1.0f / fmaxf(mys, 1e-20f) : 0.0f;
}

// ---------------- stage 5: T = diag(f) * B^T A  (C = M*N, M row-major = B^T) ----------
__global__ void __launch_bounds__(256) k_gemmT(const float* __restrict__ x) {
    int c = blockIdx.z;
    const float* M = g_B + (size_t)c * HW;   // M[j][i] = B(i,j)
    const float* N = x + (size_t)c * HW;     // A row-major
    float* C = g_T + (size_t)c * HW;
    int m0 = blockIdx.y * 64, n0 = blockIdx.x * 64;
    __shared__ float Ms[16][68], Ns[16][68];
    int t = threadIdx.x;
    int tx = t & 15, ty = t >> 4;
    float acc[4][4] = {};
    for (int k0 = 0; k0 < 256; k0 += 16) {
#pragma unroll
        for (int u = 0; u < 4; u++) {
            int id = t + 256 * u;
            int kk = id & 15, mm = id >> 4;
            Ms[kk][mm] = M[(m0 + mm) * 256 + k0 + kk];
        }
#pragma unroll
        for (int u = 0; u < 4; u++) {
            int id = t + 256 * u;
            int kk = id >> 6, nn = id & 63;
            Ns[kk][nn] = N[(k0 + kk) * 256 + n0 + nn];
        }
        __syncthreads();
#pragma unroll
        for (int kk = 0; kk < 16; kk++) {
            float a[4], b[4];
#pragma unroll
            for (int i = 0; i < 4; i++) a[i] = Ms[kk][ty * 4 + i];
#pragma unroll
            for (int j = 0; j < 4; j++) b[j] = Ns[kk][tx * 4 + j];
#pragma unroll
            for (int i = 0; i < 4; i++)
#pragma unroll
                for (int j = 0; j < 4; j++) acc[i][j] = fmaf(a[i], b[j], acc[i][j]);
        }
        __syncthreads();
    }
    const float* f = g_fact + c * 256;
#pragma unroll
    for (int i = 0; i < 4; i++) {
        float fi = f[m0 + ty * 4 + i];
#pragma unroll
        for (int j = 0; j < 4; j++)
            C[(m0 + ty * 4 + i) * 256 + n0 + tx * 4 + j] = acc[i][j] * fi;
    }
}

// ---------------- stage 6: R = B * T  (= M^T * N with M as above) ----------------
__global__ void __launch_bounds__(256) k_gemmR() {
    int c = blockIdx.z;
    const float* M = g_B + (size_t)c * HW;   // M[j][i] = B(i,j); need M^T * T
    const float* N = g_T + (size_t)c * HW;
    float* C = g_R + (size_t)c * HW;
    int m0 = blockIdx.y * 64, n0 = blockIdx.x * 64;
    __shared__ float Ms[16][68], Ns[16][68];
    int t = threadIdx.x;
    int tx = t & 15, ty = t >> 4;
    float acc[4][4] = {};
    for (int k0 = 0; k0 < 256; k0 += 16) {
#pragma unroll
        for (int u = 0; u < 4; u++) {
            int id = t + 256 * u;
            int kk = id >> 6, mm = id & 63;
            Ms[kk][mm] = M[(k0 + kk) * 256 + m0 + mm];   // M^T tile, coalesced
        }
#pragma unroll
        for (int u = 0; u < 4; u++) {
            int id = t + 256 * u;
            int kk = id >> 6, nn = id & 63;
            Ns[kk][nn] = N[(k0 + kk) * 256 + n0 + nn];
        }
        __syncthreads();
#pragma unroll
        for (int kk = 0; kk < 16; kk++) {
            float a[4], b[4];
#pragma unroll
            for (int i = 0; i < 4; i++) a[i] = Ms[kk][ty * 4 + i];
#pragma unroll
            for (int j = 0; j < 4; j++) b[j] = Ns[kk][tx * 4 + j];
#pragma unroll
            for (int i = 0; i < 4; i++)
#pragma unroll
                for (int j = 0; j < 4; j++) acc[i][j] = fmaf(a[i], b[j], acc[i][j]);
        }
        __syncthreads();
    }
#pragma unroll
    for (int i = 0; i < 4; i++)
#pragma unroll
        for (int j = 0; j < 4; j++)
            C[(m0 + ty * 4 + i) * 256 + n0 + tx * 4 + j] = acc[i][j];
}

// ---------------- stage 7: channel mean & max of recon ----------------
__global__ void k_avgmax() {
    int pix = blockIdx.x * 1024 + threadIdx.x;
    float s = 0.f, m = -3.4e38f;
    for (int c = 0; c < 256; c++) {
        float v = g_R[(size_t)c * HW + pix];
        s += v;
        m = fmaxf(m, v);
    }
    g_cat[pix]      = s * (1.0f / 256.0f);
    g_cat[HW + pix] = m;
}

// ---------------- stage 8: 7x7 conv (pad 3) + EPS clamp + sigmoid ----------------
__global__ void k_conv(const float* __restrict__ cw, float* __restrict__ out) {
    __shared__ float wsm[98];
    int tx = threadIdx.x, ty = threadIdx.y;
    int tid = ty * 32 + tx;
    if (tid < 98) wsm[tid] = cw[tid];
    __syncthreads();
    int gx = blockIdx.x * 32 + tx;
    int gy = blockIdx.y * 8 + ty;
    float acc = 0.f;
#pragma unroll
    for (int ci = 0; ci < 2; ci++) {
#pragma unroll
        for (int kh = 0; kh < 7; kh++) {
            int iy = gy + kh - 3;
            if (iy < 0 || iy > 255) continue;
#pragma unroll
            for (int kw = 0; kw < 7; kw++) {
                int ix = gx + kw - 3;
                if (ix < 0 || ix > 255) continue;
                acc = fmaf(g_cat[ci * HW + iy * 256 + ix], wsm[ci * 49 + kh * 7 + kw], acc);
            }
        }
    }
    const float EPSF = 2.220446049250313e-16f;
    if (acc < EPSF) acc = EPSF;
    out[gy * 256 + gx] = 1.0f / (1.0f + expf(-acc));
}

// ---------------- launch ----------------
extern "C" void kernel_launch(void* const* d_in, const int* in_sizes, int n_in,
                              void* d_out, int out_size) {
    const float* x  = (const float*)d_in[0];
    const float* w1 = (const float*)d_in[1];
    const float* w2 = (const float*)d_in[2];
    const float* cw = (const float*)d_in[3];
    const int*   kv = (const int*)d_in[4];

    k_stats<<<256, 256>>>(x);
    k_att<<<1, 256>>>(w1, w2, kv);
    k_tr<<<dim3(8, 8, 256), dim3(32, 8)>>>(x);
    k_jacobi<<<256, 512>>>();
    k_fact<<<256, 256>>>();
    k_gemmT<<<dim3(4, 4, 256), 256>>>(x);
    k_gemmR<<<dim3(4, 4, 256), 256>>>();
    k_avgmax<<<64, 1024>>>();
    k_conv<<<dim3(8, 32), dim3(32, 8)>>>(cw, (float*)d_out);
}